// round 1
// baseline (speedup 1.0000x reference)
#include <cuda_runtime.h>
#include <math.h>

// Problem constants (fixed by the reference)
constexpr int BB   = 2;
constexpr int SS   = 1024;
constexpr int HID  = 4096;
constexpr int NH   = 32;
constexpr int NKV  = 8;
constexpr int HD   = 128;
constexpr int ROWS = BB * SS;        // 2048

// ---------------------------------------------------------------------------
// Scratch (device globals: allocation-free per harness rules)
// ---------------------------------------------------------------------------
__device__ float g_q[(size_t)ROWS * NH * HD];    // 2048 x 4096
__device__ float g_k[(size_t)ROWS * NKV * HD];   // 2048 x 1024
__device__ float g_v[(size_t)ROWS * NKV * HD];   // 2048 x 1024
__device__ float g_o[(size_t)ROWS * NH * HD];    // 2048 x 4096

// ---------------------------------------------------------------------------
// fp32 SGEMM: C[M,N] = A[M,K] @ B[K,N], row-major, all dims multiples of tile
// 128x128 block tile, BK=8, 8x8 per thread, 256 threads.
// ---------------------------------------------------------------------------
template<int BM, int BN, int BK, int TM, int TN>
__global__ void __launch_bounds__(256)
sgemm_kernel(const float* __restrict__ A, const float* __restrict__ B,
             float* __restrict__ C, int M, int N, int K)
{
    __shared__ float As[BK][BM];   // transposed A tile
    __shared__ float Bs[BK][BN];

    const int tid  = threadIdx.x;
    const int brow = blockIdx.y;
    const int bcol = blockIdx.x;

    A += (size_t)brow * BM * K;
    B += (size_t)bcol * BN;
    C += (size_t)brow * BM * N + (size_t)bcol * BN;

    const int arow  = tid >> 1;          // 0..127
    const int acol  = (tid & 1) * 4;     // 0 or 4
    const int brw   = tid >> 5;          // 0..7
    const int bcl   = (tid & 31) * 4;    // 0..124

    const int tr = (tid >> 4) * TM;      // 0..120 step 8
    const int tc = (tid & 15) * TN;

    float acc[TM][TN] = {};
    float regM[TM], regN[TN];

    for (int k0 = 0; k0 < K; k0 += BK) {
        float4 a4 = *reinterpret_cast<const float4*>(A + (size_t)arow * K + k0 + acol);
        As[acol + 0][arow] = a4.x;
        As[acol + 1][arow] = a4.y;
        As[acol + 2][arow] = a4.z;
        As[acol + 3][arow] = a4.w;
        float4 b4 = *reinterpret_cast<const float4*>(B + (size_t)(k0 + brw) * N + bcl);
        *reinterpret_cast<float4*>(&Bs[brw][bcl]) = b4;
        __syncthreads();

        #pragma unroll
        for (int k = 0; k < BK; k++) {
            #pragma unroll
            for (int i = 0; i < TM; i++) regM[i] = As[k][tr + i];
            #pragma unroll
            for (int j = 0; j < TN; j++) regN[j] = Bs[k][tc + j];
            #pragma unroll
            for (int i = 0; i < TM; i++)
                #pragma unroll
                for (int j = 0; j < TN; j++)
                    acc[i][j] += regM[i] * regN[j];
        }
        __syncthreads();
    }

    #pragma unroll
    for (int i = 0; i < TM; i++) {
        #pragma unroll
        for (int j = 0; j < TN; j += 4) {
            float4 v;
            v.x = acc[i][j + 0]; v.y = acc[i][j + 1];
            v.z = acc[i][j + 2]; v.w = acc[i][j + 3];
            *reinterpret_cast<float4*>(C + (size_t)(tr + i) * N + tc + j) = v;
        }
    }
}

// ---------------------------------------------------------------------------
// RoPE (rotate-half), in place. t has layout [ROWS][nheads*HD].
// pair (d, d+64) per head; s = row % SS.
// ---------------------------------------------------------------------------
__global__ void rope_kernel(float* __restrict__ t,
                            const float* __restrict__ cosb,
                            const float* __restrict__ sinb,
                            int nheads, int total)
{
    int idx = blockIdx.x * blockDim.x + threadIdx.x;
    if (idx >= total) return;
    int d   = idx & 63;
    int tmp = idx >> 6;
    int hh  = tmp % nheads;
    int row = tmp / nheads;
    int s   = row & (SS - 1);
    size_t base = (size_t)row * nheads * HD + (size_t)hh * HD;
    float c  = cosb[s * 64 + d];
    float si = sinb[s * 64 + d];
    float x1 = t[base + d];
    float x2 = t[base + 64 + d];
    t[base + d]      = x1 * c  - x2 * si;
    t[base + 64 + d] = x1 * si + x2 * c;
}

// ---------------------------------------------------------------------------
// Flash attention, causal, fp32. BQ=BK=64, D=128, 256 threads.
// smem: Qt[128][65] (K-transposed, scale folded in), KV union
// (Kt[128][65] for scores, then Vs[64][128]), Ss[64][65].
// ---------------------------------------------------------------------------
constexpr int BQ  = 64;
constexpr int BKT = 64;
constexpr int QT_STR   = 65;                      // padded column count
constexpr int QT_ELEMS = HD * QT_STR;             // 8320 floats
constexpr int SMEM_FLASH_BYTES = (2 * QT_ELEMS + BQ * 65) * 4;  // 83200 B

__global__ void __launch_bounds__(256)
flash_kernel(const float* __restrict__ Q, const float* __restrict__ Kb,
             const float* __restrict__ Vb, float* __restrict__ O)
{
    extern __shared__ float sm[];
    float* Qt  = sm;                     // [128][65]
    float* KV  = sm + QT_ELEMS;          // Kt[128][65] OR Vs[64][128]
    float* Ssm = sm + 2 * QT_ELEMS;      // [64][65]

    const int tid   = threadIdx.x;
    const int qtile = blockIdx.x;        // 0..15
    const int bh    = blockIdx.y;        // 0..63
    const int b     = bh / NH;
    const int h     = bh % NH;
    const int kvh   = h / (NH / NKV);
    const int row0  = b * SS + qtile * BQ;
    const float scale = rsqrtf((float)HD);

    // ---- load Q tile, transposed, scale folded in ----
    {
        const float* qg = Q + (size_t)row0 * (NH * HD) + (size_t)h * HD;
        #pragma unroll
        for (int i = 0; i < 8; i++) {
            int idx = tid + i * 256;         // 0..2047 float4 slots
            int r   = idx >> 5;              // 0..63
            int dd  = (idx & 31) * 4;        // 0..124
            float4 v4 = *reinterpret_cast<const float4*>(qg + (size_t)r * (NH * HD) + dd);
            Qt[(dd + 0) * QT_STR + r] = v4.x * scale;
            Qt[(dd + 1) * QT_STR + r] = v4.y * scale;
            Qt[(dd + 2) * QT_STR + r] = v4.z * scale;
            Qt[(dd + 3) * QT_STR + r] = v4.w * scale;
        }
    }

    const int sr   = (tid >> 4) * 4;     // score tile row base
    const int sc   = (tid & 15) * 4;     // score tile col base
    const int orow = tid >> 2;           // O row (0..63)
    const int og   = tid & 3;            // O dim group

    float m = -INFINITY, l = 0.f;
    float oacc[32];
    #pragma unroll
    for (int j = 0; j < 32; j++) oacc[j] = 0.f;

    const int ntiles = qtile + 1;
    for (int kt = 0; kt < ntiles; kt++) {
        __syncthreads();   // KV/Ssm free from previous iteration's readers

        // ---- load K tile, transposed ----
        {
            const float* kg = Kb + (size_t)(b * SS + kt * BKT) * (NKV * HD) + (size_t)kvh * HD;
            #pragma unroll
            for (int i = 0; i < 8; i++) {
                int idx = tid + i * 256;
                int r   = idx >> 5;
                int dd  = (idx & 31) * 4;
                float4 v4 = *reinterpret_cast<const float4*>(kg + (size_t)r * (NKV * HD) + dd);
                KV[(dd + 0) * QT_STR + r] = v4.x;
                KV[(dd + 1) * QT_STR + r] = v4.y;
                KV[(dd + 2) * QT_STR + r] = v4.z;
                KV[(dd + 3) * QT_STR + r] = v4.w;
            }
        }
        __syncthreads();

        // ---- scores: S = (Q*scale) @ K^T, 64x64, 4x4 per thread ----
        float sacc[4][4] = {};
        #pragma unroll 4
        for (int d = 0; d < HD; d++) {
            float qm[4], kn[4];
            #pragma unroll
            for (int i = 0; i < 4; i++) qm[i] = Qt[d * QT_STR + sr + i];
            #pragma unroll
            for (int j = 0; j < 4; j++) kn[j] = KV[d * QT_STR + sc + j];
            #pragma unroll
            for (int i = 0; i < 4; i++)
                #pragma unroll
                for (int j = 0; j < 4; j++)
                    sacc[i][j] += qm[i] * kn[j];
        }
        const bool diag = (kt == qtile);
        #pragma unroll
        for (int i = 0; i < 4; i++)
            #pragma unroll
            for (int j = 0; j < 4; j++) {
                float v = sacc[i][j];
                if (diag && (kt * BKT + sc + j) > (qtile * BQ + sr + i)) v = -1e30f;
                Ssm[(sr + i) * 65 + sc + j] = v;
            }
        __syncthreads();   // S written; all K reads done

        // ---- load V tile into KV (plain [64][128]) ----
        {
            const float* vg = Vb + (size_t)(b * SS + kt * BKT) * (NKV * HD) + (size_t)kvh * HD;
            #pragma unroll
            for (int i = 0; i < 8; i++) {
                int idx = tid + i * 256;
                int r   = idx >> 5;
                int dd  = (idx & 31) * 4;
                *reinterpret_cast<float4*>(&KV[r * HD + dd]) =
                    *reinterpret_cast<const float4*>(vg + (size_t)r * (NKV * HD) + dd);
            }
        }

        // ---- online softmax (4 lanes per row; lanes tid%4 are warp-adjacent) ----
        {
            float pm = -INFINITY;
            #pragma unroll
            for (int k = 0; k < 16; k++)
                pm = fmaxf(pm, Ssm[orow * 65 + og * 16 + k]);
            pm = fmaxf(pm, __shfl_xor_sync(0xffffffffu, pm, 1));
            pm = fmaxf(pm, __shfl_xor_sync(0xffffffffu, pm, 2));
            float mnew = fmaxf(m, pm);
            float corr = __expf(m - mnew);
            float psum = 0.f;
            #pragma unroll
            for (int k = 0; k < 16; k++) {
                float p = __expf(Ssm[orow * 65 + og * 16 + k] - mnew);
                Ssm[orow * 65 + og * 16 + k] = p;
                psum += p;
            }
            psum += __shfl_xor_sync(0xffffffffu, psum, 1);
            psum += __shfl_xor_sync(0xffffffffu, psum, 2);
            l = l * corr + psum;
            m = mnew;
            #pragma unroll
            for (int j = 0; j < 32; j++) oacc[j] *= corr;
        }
        __syncthreads();   // V loaded + all p written

        // ---- O += P @ V. Thread covers dims og*4 + 16*j4 + (0..3): the 4
        //      og-lines per j4 land in distinct bank quads -> conflict-free ----
        {
            const float4* V4 = reinterpret_cast<const float4*>(KV);
            #pragma unroll 2
            for (int k = 0; k < BKT; k++) {
                float p = Ssm[orow * 65 + k];
                #pragma unroll
                for (int j4 = 0; j4 < 8; j4++) {
                    float4 vv = V4[k * 32 + og + 4 * j4];
                    oacc[j4 * 4 + 0] += p * vv.x;
                    oacc[j4 * 4 + 1] += p * vv.y;
                    oacc[j4 * 4 + 2] += p * vv.z;
                    oacc[j4 * 4 + 3] += p * vv.w;
                }
            }
        }
    }

    // ---- epilogue: normalize and store ----
    float inv_l = 1.f / l;
    float* optr = O + (size_t)(row0 + orow) * (NH * HD) + (size_t)h * HD;
    #pragma unroll
    for (int j4 = 0; j4 < 8; j4++) {
        float4 vv;
        vv.x = oacc[j4 * 4 + 0] * inv_l;
        vv.y = oacc[j4 * 4 + 1] * inv_l;
        vv.z = oacc[j4 * 4 + 2] * inv_l;
        vv.w = oacc[j4 * 4 + 3] * inv_l;
        *reinterpret_cast<float4*>(optr + og * 4 + j4 * 16) = vv;
    }
}

// ---------------------------------------------------------------------------
// Launch
// ---------------------------------------------------------------------------
extern "C" void kernel_launch(void* const* d_in, const int* in_sizes, int n_in,
                              void* d_out, int out_size)
{
    const float* x  = (const float*)d_in[0];
    const float* wq = (const float*)d_in[1];
    const float* wk = (const float*)d_in[2];
    const float* wv = (const float*)d_in[3];
    const float* wo = (const float*)d_in[4];
    const float* fc = (const float*)d_in[5];
    const float* fs = (const float*)d_in[6];
    // d_in[7] = start_pos (always 0; unused by the reference math)
    float* out = (float*)d_out;

    float *q, *k, *v, *o;
    cudaGetSymbolAddress((void**)&q, g_q);
    cudaGetSymbolAddress((void**)&k, g_k);
    cudaGetSymbolAddress((void**)&v, g_v);
    cudaGetSymbolAddress((void**)&o, g_o);

    dim3 blk(256);

    // QKV projections
    sgemm_kernel<128,128,8,8,8><<<dim3(NH*HD/128,  ROWS/128), blk>>>(x, wq, q, ROWS, NH*HD,  HID);
    sgemm_kernel<128,128,8,8,8><<<dim3(NKV*HD/128, ROWS/128), blk>>>(x, wk, k, ROWS, NKV*HD, HID);
    sgemm_kernel<128,128,8,8,8><<<dim3(NKV*HD/128, ROWS/128), blk>>>(x, wv, v, ROWS, NKV*HD, HID);

    // RoPE on q and k
    {
        int tq = ROWS * NH * 64;
        int tk = ROWS * NKV * 64;
        rope_kernel<<<(tq + 255) / 256, 256>>>(q, fc, fs, NH,  tq);
        rope_kernel<<<(tk + 255) / 256, 256>>>(k, fc, fs, NKV, tk);
    }

    // Flash attention
    cudaFuncSetAttribute(flash_kernel, cudaFuncAttributeMaxDynamicSharedMemorySize,
                         SMEM_FLASH_BYTES);
    flash_kernel<<<dim3(SS / BQ, BB * NH), 256, SMEM_FLASH_BYTES>>>(q, k, v, o);

    // Output projection
    sgemm_kernel<128,128,8,8,8><<<dim3(HID/128, ROWS/128), blk>>>(o, wo, out, ROWS, HID, HID);
}

// round 2
// speedup vs baseline: 1.2243x; 1.2243x over previous
#include <cuda_runtime.h>
#include <math.h>
#include <stdint.h>

// Problem constants (fixed by the reference)
constexpr int BB   = 2;
constexpr int SS   = 1024;
constexpr int HID  = 4096;
constexpr int NH   = 32;
constexpr int NKV  = 8;
constexpr int HD   = 128;
constexpr int ROWS = BB * SS;        // 2048

// ---------------------------------------------------------------------------
// Scratch (device globals: allocation-free per harness rules)
// ---------------------------------------------------------------------------
__device__ float g_q[(size_t)ROWS * NH * HD];    // 2048 x 4096
__device__ float g_k[(size_t)ROWS * NKV * HD];   // 2048 x 1024
__device__ float g_v[(size_t)ROWS * NKV * HD];   // 2048 x 1024
__device__ float g_o[(size_t)ROWS * NH * HD];    // 2048 x 4096

// ---------------------------------------------------------------------------
// tf32 helpers
// ---------------------------------------------------------------------------
__device__ __forceinline__ uint32_t f2tf32(float x) {
    uint32_t r;
    asm("cvt.rna.tf32.f32 %0, %1;" : "=r"(r) : "f"(x));
    return r;
}

__device__ __forceinline__ void mma_tf32(float (&d)[4], const uint32_t (&a)[4],
                                         const uint32_t (&b)[2]) {
    asm volatile(
        "mma.sync.aligned.m16n8k8.row.col.f32.tf32.tf32.f32 "
        "{%0,%1,%2,%3}, {%4,%5,%6,%7}, {%8,%9}, {%0,%1,%2,%3};\n"
        : "+f"(d[0]), "+f"(d[1]), "+f"(d[2]), "+f"(d[3])
        : "r"(a[0]), "r"(a[1]), "r"(a[2]), "r"(a[3]), "r"(b[0]), "r"(b[1]));
}

// ---------------------------------------------------------------------------
// 3xTF32 GEMM: C[M,N] = A[M,K] @ B[K,N], row-major.
// Block 128x128, BK=16, 256 threads (8 warps, 4(M) x 2(N), warp tile 32x64).
// Each fp32 operand is split hi/lo tf32; D += Ah*Bh + Al*Bh + Ah*Bl.
// A smem stride 20 -> A-frag LDS banks (20g+tg)%32 all distinct (conflict-free)
// B smem stride 136 -> B-frag LDS banks (8tg+g)%32 all distinct (conflict-free)
// ---------------------------------------------------------------------------
__global__ void __launch_bounds__(256)
tf32_gemm_kernel(const float* __restrict__ A, const float* __restrict__ B,
                 float* __restrict__ C, int M, int N, int K)
{
    __shared__ uint32_t Ah[128][20];
    __shared__ uint32_t Al[128][20];
    __shared__ uint32_t Bh[16][136];
    __shared__ uint32_t Bl[16][136];

    const int tid  = threadIdx.x;
    const int lane = tid & 31;
    const int warp = tid >> 5;
    const int g    = lane >> 2;      // 0..7
    const int tg   = lane & 3;       // 0..3
    const int wm   = (warp & 3) * 32;
    const int wn   = (warp >> 2) * 64;

    A += (size_t)blockIdx.y * 128 * K;
    B += (size_t)blockIdx.x * 128;
    C += (size_t)blockIdx.y * 128 * N + (size_t)blockIdx.x * 128;

    float4 rA[2], rB[2];

    // prefetch first tiles
    #pragma unroll
    for (int s = 0; s < 2; s++) {
        int slot = tid + s * 256;
        int row  = slot >> 2;
        int c    = (slot & 3) * 4;
        rA[s] = *reinterpret_cast<const float4*>(A + (size_t)row * K + c);
        int brow = slot >> 5;
        int bc   = (slot & 31) * 4;
        rB[s] = *reinterpret_cast<const float4*>(B + (size_t)brow * N + bc);
    }

    float acc[2][8][4] = {};

    for (int k0 = 0; k0 < K; k0 += 16) {
        // store prefetched tile to smem as hi/lo tf32
        #pragma unroll
        for (int s = 0; s < 2; s++) {
            int slot = tid + s * 256;
            int row  = slot >> 2;
            int c    = (slot & 3) * 4;
            float va[4] = {rA[s].x, rA[s].y, rA[s].z, rA[s].w};
            #pragma unroll
            for (int e = 0; e < 4; e++) {
                uint32_t h = f2tf32(va[e]);
                Ah[row][c + e] = h;
                Al[row][c + e] = f2tf32(va[e] - __uint_as_float(h));
            }
            int brow = slot >> 5;
            int bc   = (slot & 31) * 4;
            float vb[4] = {rB[s].x, rB[s].y, rB[s].z, rB[s].w};
            #pragma unroll
            for (int e = 0; e < 4; e++) {
                uint32_t h = f2tf32(vb[e]);
                Bh[brow][bc + e] = h;
                Bl[brow][bc + e] = f2tf32(vb[e] - __uint_as_float(h));
            }
        }
        __syncthreads();

        // prefetch next tile (overlaps with mma work below)
        if (k0 + 16 < K) {
            #pragma unroll
            for (int s = 0; s < 2; s++) {
                int slot = tid + s * 256;
                int row  = slot >> 2;
                int c    = (slot & 3) * 4;
                rA[s] = *reinterpret_cast<const float4*>(A + (size_t)row * K + k0 + 16 + c);
                int brow = slot >> 5;
                int bc   = (slot & 31) * 4;
                rB[s] = *reinterpret_cast<const float4*>(B + (size_t)(k0 + 16 + brow) * N + bc);
            }
        }

        #pragma unroll
        for (int ko = 0; ko < 2; ko++) {
            uint32_t ah[2][4], al_[2][4];
            #pragma unroll
            for (int i = 0; i < 2; i++) {
                int r0 = wm + 16 * i + g;
                int c0 = 8 * ko + tg;
                ah[i][0]  = Ah[r0][c0];     ah[i][1]  = Ah[r0 + 8][c0];
                ah[i][2]  = Ah[r0][c0 + 4]; ah[i][3]  = Ah[r0 + 8][c0 + 4];
                al_[i][0] = Al[r0][c0];     al_[i][1] = Al[r0 + 8][c0];
                al_[i][2] = Al[r0][c0 + 4]; al_[i][3] = Al[r0 + 8][c0 + 4];
            }
            #pragma unroll
            for (int j = 0; j < 8; j++) {
                int col = wn + 8 * j + g;
                int r0  = 8 * ko + tg;
                uint32_t bh[2] = {Bh[r0][col], Bh[r0 + 4][col]};
                uint32_t bl[2] = {Bl[r0][col], Bl[r0 + 4][col]};
                #pragma unroll
                for (int i = 0; i < 2; i++) {
                    mma_tf32(acc[i][j], ah[i],  bh);
                    mma_tf32(acc[i][j], al_[i], bh);
                    mma_tf32(acc[i][j], ah[i],  bl);
                }
            }
        }
        __syncthreads();
    }

    // epilogue
    #pragma unroll
    for (int i = 0; i < 2; i++) {
        #pragma unroll
        for (int j = 0; j < 8; j++) {
            int row = wm + 16 * i + g;
            int col = wn + 8 * j + 2 * tg;
            float2 v01; v01.x = acc[i][j][0]; v01.y = acc[i][j][1];
            float2 v23; v23.x = acc[i][j][2]; v23.y = acc[i][j][3];
            *reinterpret_cast<float2*>(C + (size_t)row * N + col)       = v01;
            *reinterpret_cast<float2*>(C + (size_t)(row + 8) * N + col) = v23;
        }
    }
}

// ---------------------------------------------------------------------------
// RoPE (rotate-half), in place. t has layout [ROWS][nheads*HD].
// ---------------------------------------------------------------------------
__global__ void rope_kernel(float* __restrict__ t,
                            const float* __restrict__ cosb,
                            const float* __restrict__ sinb,
                            int nheads, int total)
{
    int idx = blockIdx.x * blockDim.x + threadIdx.x;
    if (idx >= total) return;
    int d   = idx & 63;
    int tmp = idx >> 6;
    int hh  = tmp % nheads;
    int row = tmp / nheads;
    int s   = row & (SS - 1);
    size_t base = (size_t)row * nheads * HD + (size_t)hh * HD;
    float c  = cosb[s * 64 + d];
    float si = sinb[s * 64 + d];
    float x1 = t[base + d];
    float x2 = t[base + 64 + d];
    t[base + d]      = x1 * c  - x2 * si;
    t[base + 64 + d] = x1 * si + x2 * c;
}

// ---------------------------------------------------------------------------
// Flash attention, causal, fp32. BQ=BK=64, D=128, 256 threads.
// (proven correct in round 1; tensor-core conversion is the next-round target)
// ---------------------------------------------------------------------------
constexpr int BQ  = 64;
constexpr int BKT = 64;
constexpr int QT_STR   = 65;
constexpr int QT_ELEMS = HD * QT_STR;
constexpr int SMEM_FLASH_BYTES = (2 * QT_ELEMS + BQ * 65) * 4;  // 83200 B

__global__ void __launch_bounds__(256)
flash_kernel(const float* __restrict__ Q, const float* __restrict__ Kb,
             const float* __restrict__ Vb, float* __restrict__ O)
{
    extern __shared__ float sm[];
    float* Qt  = sm;                     // [128][65]
    float* KV  = sm + QT_ELEMS;          // Kt[128][65] OR Vs[64][128]
    float* Ssm = sm + 2 * QT_ELEMS;      // [64][65]

    const int tid   = threadIdx.x;
    const int qtile = blockIdx.x;
    const int bh    = blockIdx.y;
    const int b     = bh / NH;
    const int h     = bh % NH;
    const int kvh   = h / (NH / NKV);
    const int row0  = b * SS + qtile * BQ;
    const float scale = rsqrtf((float)HD);

    {
        const float* qg = Q + (size_t)row0 * (NH * HD) + (size_t)h * HD;
        #pragma unroll
        for (int i = 0; i < 8; i++) {
            int idx = tid + i * 256;
            int r   = idx >> 5;
            int dd  = (idx & 31) * 4;
            float4 v4 = *reinterpret_cast<const float4*>(qg + (size_t)r * (NH * HD) + dd);
            Qt[(dd + 0) * QT_STR + r] = v4.x * scale;
            Qt[(dd + 1) * QT_STR + r] = v4.y * scale;
            Qt[(dd + 2) * QT_STR + r] = v4.z * scale;
            Qt[(dd + 3) * QT_STR + r] = v4.w * scale;
        }
    }

    const int sr   = (tid >> 4) * 4;
    const int sc   = (tid & 15) * 4;
    const int orow = tid >> 2;
    const int og   = tid & 3;

    float m = -INFINITY, l = 0.f;
    float oacc[32];
    #pragma unroll
    for (int j = 0; j < 32; j++) oacc[j] = 0.f;

    const int ntiles = qtile + 1;
    for (int kt = 0; kt < ntiles; kt++) {
        __syncthreads();

        {
            const float* kg = Kb + (size_t)(b * SS + kt * BKT) * (NKV * HD) + (size_t)kvh * HD;
            #pragma unroll
            for (int i = 0; i < 8; i++) {
                int idx = tid + i * 256;
                int r   = idx >> 5;
                int dd  = (idx & 31) * 4;
                float4 v4 = *reinterpret_cast<const float4*>(kg + (size_t)r * (NKV * HD) + dd);
                KV[(dd + 0) * QT_STR + r] = v4.x;
                KV[(dd + 1) * QT_STR + r] = v4.y;
                KV[(dd + 2) * QT_STR + r] = v4.z;
                KV[(dd + 3) * QT_STR + r] = v4.w;
            }
        }
        __syncthreads();

        float sacc[4][4] = {};
        #pragma unroll 4
        for (int d = 0; d < HD; d++) {
            float qm[4], kn[4];
            #pragma unroll
            for (int i = 0; i < 4; i++) qm[i] = Qt[d * QT_STR + sr + i];
            #pragma unroll
            for (int j = 0; j < 4; j++) kn[j] = KV[d * QT_STR + sc + j];
            #pragma unroll
            for (int i = 0; i < 4; i++)
                #pragma unroll
                for (int j = 0; j < 4; j++)
                    sacc[i][j] += qm[i] * kn[j];
        }
        const bool diag = (kt == qtile);
        #pragma unroll
        for (int i = 0; i < 4; i++)
            #pragma unroll
            for (int j = 0; j < 4; j++) {
                float v = sacc[i][j];
                if (diag && (kt * BKT + sc + j) > (qtile * BQ + sr + i)) v = -1e30f;
                Ssm[(sr + i) * 65 + sc + j] = v;
            }
        __syncthreads();

        {
            const float* vg = Vb + (size_t)(b * SS + kt * BKT) * (NKV * HD) + (size_t)kvh * HD;
            #pragma unroll
            for (int i = 0; i < 8; i++) {
                int idx = tid + i * 256;
                int r   = idx >> 5;
                int dd  = (idx & 31) * 4;
                *reinterpret_cast<float4*>(&KV[r * HD + dd]) =
                    *reinterpret_cast<const float4*>(vg + (size_t)r * (NKV * HD) + dd);
            }
        }

        {
            float pm = -INFINITY;
            #pragma unroll
            for (int k = 0; k < 16; k++)
                pm = fmaxf(pm, Ssm[orow * 65 + og * 16 + k]);
            pm = fmaxf(pm, __shfl_xor_sync(0xffffffffu, pm, 1));
            pm = fmaxf(pm, __shfl_xor_sync(0xffffffffu, pm, 2));
            float mnew = fmaxf(m, pm);
            float corr = __expf(m - mnew);
            float psum = 0.f;
            #pragma unroll
            for (int k = 0; k < 16; k++) {
                float p = __expf(Ssm[orow * 65 + og * 16 + k] - mnew);
                Ssm[orow * 65 + og * 16 + k] = p;
                psum += p;
            }
            psum += __shfl_xor_sync(0xffffffffu, psum, 1);
            psum += __shfl_xor_sync(0xffffffffu, psum, 2);
            l = l * corr + psum;
            m = mnew;
            #pragma unroll
            for (int j = 0; j < 32; j++) oacc[j] *= corr;
        }
        __syncthreads();

        {
            const float4* V4 = reinterpret_cast<const float4*>(KV);
            #pragma unroll 2
            for (int k = 0; k < BKT; k++) {
                float p = Ssm[orow * 65 + k];
                #pragma unroll
                for (int j4 = 0; j4 < 8; j4++) {
                    float4 vv = V4[k * 32 + og + 4 * j4];
                    oacc[j4 * 4 + 0] += p * vv.x;
                    oacc[j4 * 4 + 1] += p * vv.y;
                    oacc[j4 * 4 + 2] += p * vv.z;
                    oacc[j4 * 4 + 3] += p * vv.w;
                }
            }
        }
    }

    float inv_l = 1.f / l;
    float* optr = O + (size_t)(row0 + orow) * (NH * HD) + (size_t)h * HD;
    #pragma unroll
    for (int j4 = 0; j4 < 8; j4++) {
        float4 vv;
        vv.x = oacc[j4 * 4 + 0] * inv_l;
        vv.y = oacc[j4 * 4 + 1] * inv_l;
        vv.z = oacc[j4 * 4 + 2] * inv_l;
        vv.w = oacc[j4 * 4 + 3] * inv_l;
        *reinterpret_cast<float4*>(optr + og * 4 + j4 * 16) = vv;
    }
}

// ---------------------------------------------------------------------------
// Launch
// ---------------------------------------------------------------------------
extern "C" void kernel_launch(void* const* d_in, const int* in_sizes, int n_in,
                              void* d_out, int out_size)
{
    const float* x  = (const float*)d_in[0];
    const float* wq = (const float*)d_in[1];
    const float* wk = (const float*)d_in[2];
    const float* wv = (const float*)d_in[3];
    const float* wo = (const float*)d_in[4];
    const float* fc = (const float*)d_in[5];
    const float* fs = (const float*)d_in[6];
    float* out = (float*)d_out;

    float *q, *k, *v, *o;
    cudaGetSymbolAddress((void**)&q, g_q);
    cudaGetSymbolAddress((void**)&k, g_k);
    cudaGetSymbolAddress((void**)&v, g_v);
    cudaGetSymbolAddress((void**)&o, g_o);

    dim3 blk(256);

    // QKV projections (3xTF32 tensor-core GEMM)
    tf32_gemm_kernel<<<dim3(NH*HD/128,  ROWS/128), blk>>>(x, wq, q, ROWS, NH*HD,  HID);
    tf32_gemm_kernel<<<dim3(NKV*HD/128, ROWS/128), blk>>>(x, wk, k, ROWS, NKV*HD, HID);
    tf32_gemm_kernel<<<dim3(NKV*HD/128, ROWS/128), blk>>>(x, wv, v, ROWS, NKV*HD, HID);

    // RoPE on q and k
    {
        int tq = ROWS * NH * 64;
        int tk = ROWS * NKV * 64;
        rope_kernel<<<(tq + 255) / 256, 256>>>(q, fc, fs, NH,  tq);
        rope_kernel<<<(tk + 255) / 256, 256>>>(k, fc, fs, NKV, tk);
    }

    // Flash attention (fp32)
    cudaFuncSetAttribute(flash_kernel, cudaFuncAttributeMaxDynamicSharedMemorySize,
                         SMEM_FLASH_BYTES);
    flash_kernel<<<dim3(SS / BQ, BB * NH), 256, SMEM_FLASH_BYTES>>>(q, k, v, o);

    // Output projection (3xTF32 tensor-core GEMM)
    tf32_gemm_kernel<<<dim3(HID/128, ROWS/128), blk>>>(o, wo, out, ROWS, HID, HID);
}

// round 4
// speedup vs baseline: 1.5611x; 1.2752x over previous
#include <cuda_runtime.h>
#include <math.h>
#include <stdint.h>

// Problem constants (fixed by the reference)
constexpr int BB   = 2;
constexpr int SS   = 1024;
constexpr int HID  = 4096;
constexpr int NH   = 32;
constexpr int NKV  = 8;
constexpr int HD   = 128;
constexpr int ROWS = BB * SS;        // 2048

// ---------------------------------------------------------------------------
// Scratch (device globals: allocation-free per harness rules)
// ---------------------------------------------------------------------------
__device__ float g_q[(size_t)ROWS * NH * HD];
__device__ float g_k[(size_t)ROWS * NKV * HD];
__device__ float g_v[(size_t)ROWS * NKV * HD];
__device__ float g_o[(size_t)ROWS * NH * HD];

// ---------------------------------------------------------------------------
// tf32 helpers
// ---------------------------------------------------------------------------
__device__ __forceinline__ uint32_t f2tf32(float x) {
    uint32_t r;
    asm("cvt.rna.tf32.f32 %0, %1;" : "=r"(r) : "f"(x));
    return r;
}

__device__ __forceinline__ void mma_tf32(float (&d)[4], const uint32_t (&a)[4],
                                         const uint32_t (&b)[2]) {
    asm volatile(
        "mma.sync.aligned.m16n8k8.row.col.f32.tf32.tf32.f32 "
        "{%0,%1,%2,%3}, {%4,%5,%6,%7}, {%8,%9}, {%0,%1,%2,%3};\n"
        : "+f"(d[0]), "+f"(d[1]), "+f"(d[2]), "+f"(d[3])
        : "r"(a[0]), "r"(a[1]), "r"(a[2]), "r"(a[3]), "r"(b[0]), "r"(b[1]));
}

// ---------------------------------------------------------------------------
// 3xTF32 GEMM, double-buffered. C[M,N] = A[M,K] @ B[K,N] row-major.
// Block 128x128, BK=16, 256 threads (8 warps, 4(M) x 2(N), warp 32x64).
// ---------------------------------------------------------------------------
constexpr int GEMM_AH = 128 * 20;
constexpr int GEMM_BH = 16 * 136;
constexpr int GEMM_BUF = 2 * GEMM_AH + 2 * GEMM_BH;   // 9472 u32
constexpr int GEMM_SMEM_BYTES = 2 * GEMM_BUF * 4;     // 75776 B

__global__ void __launch_bounds__(256)
tf32_gemm_kernel(const float* __restrict__ A, const float* __restrict__ B,
                 float* __restrict__ C, int M, int N, int K)
{
    extern __shared__ uint32_t gsm[];

    const int tid  = threadIdx.x;
    const int lane = tid & 31;
    const int warp = tid >> 5;
    const int g    = lane >> 2;
    const int tg   = lane & 3;
    const int wm   = (warp & 3) * 32;
    const int wn   = (warp >> 2) * 64;

    A += (size_t)blockIdx.y * 128 * K;
    B += (size_t)blockIdx.x * 128;
    C += (size_t)blockIdx.y * 128 * N + (size_t)blockIdx.x * 128;

    float4 rA[2], rB[2];

    auto prefetch = [&](int k0) {
        #pragma unroll
        for (int s = 0; s < 2; s++) {
            int slot = tid + s * 256;
            rA[s] = *reinterpret_cast<const float4*>(
                A + (size_t)(slot >> 2) * K + k0 + (slot & 3) * 4);
            rB[s] = *reinterpret_cast<const float4*>(
                B + (size_t)(k0 + (slot >> 5)) * N + (slot & 31) * 4);
        }
    };
    auto stash = [&](int buf) {
        uint32_t* Ah = gsm + buf * GEMM_BUF;
        uint32_t* Al = Ah + GEMM_AH;
        uint32_t* Bh = Al + GEMM_AH;
        uint32_t* Bl = Bh + GEMM_BH;
        #pragma unroll
        for (int s = 0; s < 2; s++) {
            int slot = tid + s * 256;
            int row  = slot >> 2;
            int c    = (slot & 3) * 4;
            float va[4] = {rA[s].x, rA[s].y, rA[s].z, rA[s].w};
            #pragma unroll
            for (int e = 0; e < 4; e++) {
                uint32_t h = f2tf32(va[e]);
                Ah[row * 20 + c + e] = h;
                Al[row * 20 + c + e] = f2tf32(va[e] - __uint_as_float(h));
            }
            int br = slot >> 5;
            int bc = (slot & 31) * 4;
            float vb[4] = {rB[s].x, rB[s].y, rB[s].z, rB[s].w};
            #pragma unroll
            for (int e = 0; e < 4; e++) {
                uint32_t h = f2tf32(vb[e]);
                Bh[br * 136 + bc + e] = h;
                Bl[br * 136 + bc + e] = f2tf32(vb[e] - __uint_as_float(h));
            }
        }
    };

    prefetch(0);
    stash(0);
    __syncthreads();

    float acc[2][8][4] = {};
    const int nkt = K / 16;

    for (int kt = 0; kt < nkt; kt++) {
        const int cur = kt & 1;
        const bool more = (kt + 1 < nkt);
        if (more) prefetch((kt + 1) * 16);

        uint32_t* Ah = gsm + cur * GEMM_BUF;
        uint32_t* Al = Ah + GEMM_AH;
        uint32_t* Bh = Al + GEMM_AH;
        uint32_t* Bl = Bh + GEMM_BH;

        #pragma unroll
        for (int ko = 0; ko < 2; ko++) {
            uint32_t ah[2][4], al_[2][4];
            #pragma unroll
            for (int i = 0; i < 2; i++) {
                int r0 = wm + 16 * i + g;
                int c0 = 8 * ko + tg;
                ah[i][0]  = Ah[r0 * 20 + c0];       ah[i][1]  = Ah[(r0 + 8) * 20 + c0];
                ah[i][2]  = Ah[r0 * 20 + c0 + 4];   ah[i][3]  = Ah[(r0 + 8) * 20 + c0 + 4];
                al_[i][0] = Al[r0 * 20 + c0];       al_[i][1] = Al[(r0 + 8) * 20 + c0];
                al_[i][2] = Al[r0 * 20 + c0 + 4];   al_[i][3] = Al[(r0 + 8) * 20 + c0 + 4];
            }
            #pragma unroll
            for (int j = 0; j < 8; j++) {
                int col = wn + 8 * j + g;
                int r0  = 8 * ko + tg;
                uint32_t bh[2] = {Bh[r0 * 136 + col], Bh[(r0 + 4) * 136 + col]};
                uint32_t bl[2] = {Bl[r0 * 136 + col], Bl[(r0 + 4) * 136 + col]};
                #pragma unroll
                for (int i = 0; i < 2; i++) {
                    mma_tf32(acc[i][j], ah[i],  bh);
                    mma_tf32(acc[i][j], al_[i], bh);
                    mma_tf32(acc[i][j], ah[i],  bl);
                }
            }
        }
        if (more) stash(cur ^ 1);
        __syncthreads();
    }

    #pragma unroll
    for (int i = 0; i < 2; i++) {
        #pragma unroll
        for (int j = 0; j < 8; j++) {
            int row = wm + 16 * i + g;
            int col = wn + 8 * j + 2 * tg;
            float2 v01; v01.x = acc[i][j][0]; v01.y = acc[i][j][1];
            float2 v23; v23.x = acc[i][j][2]; v23.y = acc[i][j][3];
            *reinterpret_cast<float2*>(C + (size_t)row * N + col)       = v01;
            *reinterpret_cast<float2*>(C + (size_t)(row + 8) * N + col) = v23;
        }
    }
}

// ---------------------------------------------------------------------------
// RoPE (rotate-half), in place.
// ---------------------------------------------------------------------------
__global__ void rope_kernel(float* __restrict__ t,
                            const float* __restrict__ cosb,
                            const float* __restrict__ sinb,
                            int nheads, int total)
{
    int idx = blockIdx.x * blockDim.x + threadIdx.x;
    if (idx >= total) return;
    int d   = idx & 63;
    int tmp = idx >> 6;
    int hh  = tmp % nheads;
    int row = tmp / nheads;
    int s   = row & (SS - 1);
    size_t base = (size_t)row * nheads * HD + (size_t)hh * HD;
    float c  = cosb[s * 64 + d];
    float si = sinb[s * 64 + d];
    float x1 = t[base + d];
    float x2 = t[base + 64 + d];
    t[base + d]      = x1 * c  - x2 * si;
    t[base + 64 + d] = x1 * si + x2 * c;
}

// ---------------------------------------------------------------------------
// Flash attention, tensor cores (3xTF32), causal. BQ=BK=64, D=128, 256 thr.
// STRIDES FIXED: rows are 128 dims wide ->
//   QSTR=KSTR=132 (>=128, ==4 mod 32: A/B-frag banks (4g+tg) distinct)
//   VSTR=136      (>=128, ==8 mod 32: V-frag banks (8tg+g) distinct)
//   PSTR=68       (P is 64 wide)
// V kept as raw fp32 in smem (split hi/lo on the fly) to fit the smem cap.
// ---------------------------------------------------------------------------
constexpr int QSTR = 132, KSTR = 132, VSTR = 136, PSTR = 68, SSTR = 65;
constexpr int F_SM_FLOATS = 64*QSTR*2 + 64*KSTR*2 + 64*VSTR + 64*SSTR + 64*PSTR*2 + 192;
constexpr int F_SM_BYTES  = F_SM_FLOATS * 4;   // 222208 B (cap 232448)

__global__ void __launch_bounds__(256)
flash_mma_kernel(const float* __restrict__ Qg, const float* __restrict__ Kg,
                 const float* __restrict__ Vg, float* __restrict__ Og)
{
    extern __shared__ float fsm[];
    float* Qh = fsm;               float* Ql = Qh + 64 * QSTR;
    float* Kh = Ql + 64 * QSTR;    float* Kl = Kh + 64 * KSTR;
    float* Vs = Kl + 64 * KSTR;
    float* Sr = Vs + 64 * VSTR;
    float* Ph = Sr + 64 * SSTR;    float* Pl = Ph + 64 * PSTR;
    float* s_m = Pl + 64 * PSTR;   float* s_l = s_m + 64;   float* s_c = s_l + 64;

    const int tid  = threadIdx.x;
    const int lane = tid & 31;
    const int warp = tid >> 5;
    const int g    = lane >> 2;
    const int tg   = lane & 3;
    const int wm   = (warp & 3) * 16;
    const int wnS  = (warp >> 2) * 32;
    const int wnP  = (warp >> 2) * 64;

    const int qtile = gridDim.x - 1 - blockIdx.x;
    const int bh  = blockIdx.y;
    const int b   = bh / NH;
    const int h   = bh % NH;
    const int kvh = h / (NH / NKV);
    const int row0 = b * SS + qtile * 64;
    const float scale = rsqrtf((float)HD);

    // ---- load + split Q (scale folded) ----
    {
        const float* qg = Qg + (size_t)row0 * (NH * HD) + (size_t)h * HD;
        #pragma unroll
        for (int i = 0; i < 8; i++) {
            int idx = tid + i * 256;
            int r   = idx >> 5;
            int dd  = (idx & 31) * 4;
            float4 v = *reinterpret_cast<const float4*>(qg + (size_t)r * (NH * HD) + dd);
            float f[4] = {v.x * scale, v.y * scale, v.z * scale, v.w * scale};
            uint4 hv, lv;
            uint32_t t0 = f2tf32(f[0]); hv.x = t0; lv.x = f2tf32(f[0] - __uint_as_float(t0));
            uint32_t t1 = f2tf32(f[1]); hv.y = t1; lv.y = f2tf32(f[1] - __uint_as_float(t1));
            uint32_t t2 = f2tf32(f[2]); hv.z = t2; lv.z = f2tf32(f[2] - __uint_as_float(t2));
            uint32_t t3 = f2tf32(f[3]); hv.w = t3; lv.w = f2tf32(f[3] - __uint_as_float(t3));
            *reinterpret_cast<uint4*>(&Qh[r * QSTR + dd]) = hv;
            *reinterpret_cast<uint4*>(&Ql[r * QSTR + dd]) = lv;
        }
    }
    if (tid < 64) { s_m[tid] = -INFINITY; s_l[tid] = 0.f; }

    float oacc[8][4] = {};

    for (int kt = 0; kt <= qtile; kt++) {
        __syncthreads();

        // ---- load tiles: K split hi/lo, V raw fp32 ----
        {
            const float* kg = Kg + (size_t)(b * SS + kt * 64) * (NKV * HD) + (size_t)kvh * HD;
            const float* vg = Vg + (size_t)(b * SS + kt * 64) * (NKV * HD) + (size_t)kvh * HD;
            #pragma unroll
            for (int i = 0; i < 8; i++) {
                int idx = tid + i * 256;
                int r   = idx >> 5;
                int dd  = (idx & 31) * 4;
                float4 kv = *reinterpret_cast<const float4*>(kg + (size_t)r * (NKV * HD) + dd);
                float f[4] = {kv.x, kv.y, kv.z, kv.w};
                uint4 hv, lv;
                uint32_t t0 = f2tf32(f[0]); hv.x = t0; lv.x = f2tf32(f[0] - __uint_as_float(t0));
                uint32_t t1 = f2tf32(f[1]); hv.y = t1; lv.y = f2tf32(f[1] - __uint_as_float(t1));
                uint32_t t2 = f2tf32(f[2]); hv.z = t2; lv.z = f2tf32(f[2] - __uint_as_float(t2));
                uint32_t t3 = f2tf32(f[3]); hv.w = t3; lv.w = f2tf32(f[3] - __uint_as_float(t3));
                *reinterpret_cast<uint4*>(&Kh[r * KSTR + dd]) = hv;
                *reinterpret_cast<uint4*>(&Kl[r * KSTR + dd]) = lv;
                *reinterpret_cast<float4*>(&Vs[r * VSTR + dd]) =
                    *reinterpret_cast<const float4*>(vg + (size_t)r * (NKV * HD) + dd);
            }
        }
        __syncthreads();

        // ---- scores: S = Q K^T (3xTF32) ----
        float sacc[4][4] = {};
        #pragma unroll
        for (int k8 = 0; k8 < 16; k8++) {
            const int k = k8 * 8;
            uint32_t ah[4], al[4];
            ah[0] = __float_as_uint(Qh[(wm + g) * QSTR + k + tg]);
            ah[1] = __float_as_uint(Qh[(wm + g + 8) * QSTR + k + tg]);
            ah[2] = __float_as_uint(Qh[(wm + g) * QSTR + k + tg + 4]);
            ah[3] = __float_as_uint(Qh[(wm + g + 8) * QSTR + k + tg + 4]);
            al[0] = __float_as_uint(Ql[(wm + g) * QSTR + k + tg]);
            al[1] = __float_as_uint(Ql[(wm + g + 8) * QSTR + k + tg]);
            al[2] = __float_as_uint(Ql[(wm + g) * QSTR + k + tg + 4]);
            al[3] = __float_as_uint(Ql[(wm + g + 8) * QSTR + k + tg + 4]);
            #pragma unroll
            for (int nt = 0; nt < 4; nt++) {
                const int col = wnS + nt * 8 + g;
                uint32_t kb[2]  = {__float_as_uint(Kh[col * KSTR + k + tg]),
                                   __float_as_uint(Kh[col * KSTR + k + tg + 4])};
                uint32_t kl2[2] = {__float_as_uint(Kl[col * KSTR + k + tg]),
                                   __float_as_uint(Kl[col * KSTR + k + tg + 4])};
                mma_tf32(sacc[nt], ah, kb);
                mma_tf32(sacc[nt], al, kb);
                mma_tf32(sacc[nt], ah, kl2);
            }
        }

        // ---- write masked S ----
        {
            const bool diag = (kt == qtile);
            const int r0 = wm + g;
            #pragma unroll
            for (int nt = 0; nt < 4; nt++) {
                int colb = wnS + nt * 8 + 2 * tg;
                float v0 = sacc[nt][0], v1 = sacc[nt][1];
                float v2 = sacc[nt][2], v3 = sacc[nt][3];
                if (diag) {
                    if (colb     > r0)     v0 = -1e30f;
                    if (colb + 1 > r0)     v1 = -1e30f;
                    if (colb     > r0 + 8) v2 = -1e30f;
                    if (colb + 1 > r0 + 8) v3 = -1e30f;
                }
                Sr[r0 * SSTR + colb]           = v0;
                Sr[r0 * SSTR + colb + 1]       = v1;
                Sr[(r0 + 8) * SSTR + colb]     = v2;
                Sr[(r0 + 8) * SSTR + colb + 1] = v3;
            }
        }
        __syncthreads();

        // ---- online softmax; write split P ----
        {
            const int orow = tid >> 2, og = tid & 3;
            const float* srow = Sr + orow * SSTR + og * 16;
            float pm = -INFINITY;
            #pragma unroll
            for (int k = 0; k < 16; k++) pm = fmaxf(pm, srow[k]);
            pm = fmaxf(pm, __shfl_xor_sync(0xffffffffu, pm, 1));
            pm = fmaxf(pm, __shfl_xor_sync(0xffffffffu, pm, 2));
            float mold = s_m[orow];
            float mnew = fmaxf(mold, pm);
            float corr = __expf(mold - mnew);
            float psum = 0.f;
            float* ph = Ph + orow * PSTR + og * 16;
            float* pl = Pl + orow * PSTR + og * 16;
            #pragma unroll
            for (int k = 0; k < 16; k++) {
                float p = __expf(srow[k] - mnew);
                uint32_t hb = f2tf32(p);
                ph[k] = __uint_as_float(hb);
                pl[k] = __uint_as_float(f2tf32(p - __uint_as_float(hb)));
                psum += p;
            }
            psum += __shfl_xor_sync(0xffffffffu, psum, 1);
            psum += __shfl_xor_sync(0xffffffffu, psum, 2);
            if (og == 0) {
                s_m[orow] = mnew;
                s_c[orow] = corr;
                s_l[orow] = s_l[orow] * corr + psum;
            }
        }
        __syncthreads();

        // ---- O = O*corr + P V (3xTF32, V split on the fly) ----
        {
            const float c0 = s_c[wm + g], c1 = s_c[wm + g + 8];
            #pragma unroll
            for (int nt = 0; nt < 8; nt++) {
                oacc[nt][0] *= c0; oacc[nt][1] *= c0;
                oacc[nt][2] *= c1; oacc[nt][3] *= c1;
            }
            #pragma unroll
            for (int k8 = 0; k8 < 8; k8++) {
                const int k = k8 * 8;
                uint32_t pa[4], pb[4];
                pa[0] = __float_as_uint(Ph[(wm + g) * PSTR + k + tg]);
                pa[1] = __float_as_uint(Ph[(wm + g + 8) * PSTR + k + tg]);
                pa[2] = __float_as_uint(Ph[(wm + g) * PSTR + k + tg + 4]);
                pa[3] = __float_as_uint(Ph[(wm + g + 8) * PSTR + k + tg + 4]);
                pb[0] = __float_as_uint(Pl[(wm + g) * PSTR + k + tg]);
                pb[1] = __float_as_uint(Pl[(wm + g + 8) * PSTR + k + tg]);
                pb[2] = __float_as_uint(Pl[(wm + g) * PSTR + k + tg + 4]);
                pb[3] = __float_as_uint(Pl[(wm + g + 8) * PSTR + k + tg + 4]);
                #pragma unroll
                for (int nt = 0; nt < 8; nt++) {
                    const int coln = wnP + nt * 8 + g;
                    float v0 = Vs[(k + tg) * VSTR + coln];
                    float v1 = Vs[(k + tg + 4) * VSTR + coln];
                    uint32_t h0 = f2tf32(v0), h1 = f2tf32(v1);
                    uint32_t vb[2]  = {h0, h1};
                    uint32_t vl2[2] = {f2tf32(v0 - __uint_as_float(h0)),
                                       f2tf32(v1 - __uint_as_float(h1))};
                    mma_tf32(oacc[nt], pa, vb);
                    mma_tf32(oacc[nt], pb, vb);
                    mma_tf32(oacc[nt], pa, vl2);
                }
            }
        }
    }

    // ---- epilogue ----
    {
        const float inv0 = 1.f / s_l[wm + g];
        const float inv1 = 1.f / s_l[wm + g + 8];
        float* o0 = Og + (size_t)(row0 + wm + g) * (NH * HD) + (size_t)h * HD;
        float* o1 = Og + (size_t)(row0 + wm + g + 8) * (NH * HD) + (size_t)h * HD;
        #pragma unroll
        for (int nt = 0; nt < 8; nt++) {
            int col = wnP + nt * 8 + 2 * tg;
            float2 a;  a.x  = oacc[nt][0] * inv0; a.y  = oacc[nt][1] * inv0;
            float2 b2; b2.x = oacc[nt][2] * inv1; b2.y = oacc[nt][3] * inv1;
            *reinterpret_cast<float2*>(o0 + col) = a;
            *reinterpret_cast<float2*>(o1 + col) = b2;
        }
    }
}

// ---------------------------------------------------------------------------
// Launch
// ---------------------------------------------------------------------------
extern "C" void kernel_launch(void* const* d_in, const int* in_sizes, int n_in,
                              void* d_out, int out_size)
{
    const float* x  = (const float*)d_in[0];
    const float* wq = (const float*)d_in[1];
    const float* wk = (const float*)d_in[2];
    const float* wv = (const float*)d_in[3];
    const float* wo = (const float*)d_in[4];
    const float* fc = (const float*)d_in[5];
    const float* fs = (const float*)d_in[6];
    float* out = (float*)d_out;

    float *q, *k, *v, *o;
    cudaGetSymbolAddress((void**)&q, g_q);
    cudaGetSymbolAddress((void**)&k, g_k);
    cudaGetSymbolAddress((void**)&v, g_v);
    cudaGetSymbolAddress((void**)&o, g_o);

    dim3 blk(256);

    cudaFuncSetAttribute(tf32_gemm_kernel, cudaFuncAttributeMaxDynamicSharedMemorySize,
                         GEMM_SMEM_BYTES);
    cudaFuncSetAttribute(flash_mma_kernel, cudaFuncAttributeMaxDynamicSharedMemorySize,
                         F_SM_BYTES);

    // QKV projections (3xTF32, double-buffered)
    tf32_gemm_kernel<<<dim3(NH*HD/128,  ROWS/128), blk, GEMM_SMEM_BYTES>>>(x, wq, q, ROWS, NH*HD,  HID);
    tf32_gemm_kernel<<<dim3(NKV*HD/128, ROWS/128), blk, GEMM_SMEM_BYTES>>>(x, wk, k, ROWS, NKV*HD, HID);
    tf32_gemm_kernel<<<dim3(NKV*HD/128, ROWS/128), blk, GEMM_SMEM_BYTES>>>(x, wv, v, ROWS, NKV*HD, HID);

    // RoPE on q and k
    {
        int tq = ROWS * NH * 64;
        int tk = ROWS * NKV * 64;
        rope_kernel<<<(tq + 255) / 256, 256>>>(q, fc, fs, NH,  tq);
        rope_kernel<<<(tk + 255) / 256, 256>>>(k, fc, fs, NKV, tk);
    }

    // Flash attention (tensor-core 3xTF32)
    flash_mma_kernel<<<dim3(SS / 64, BB * NH), blk, F_SM_BYTES>>>(q, k, v, o);

    // Output projection
    tf32_gemm_kernel<<<dim3(HID/128, ROWS/128), blk, GEMM_SMEM_BYTES>>>(o, wo, out, ROWS, HID, HID);
}

// round 6
// speedup vs baseline: 1.6741x; 1.0724x over previous
#include <cuda_runtime.h>
#include <math.h>
#include <stdint.h>

// Problem constants (fixed by the reference)
constexpr int BB   = 2;
constexpr int SS   = 1024;
constexpr int HID  = 4096;
constexpr int NH   = 32;
constexpr int NKV  = 8;
constexpr int HD   = 128;
constexpr int ROWS = BB * SS;        // 2048

// ---------------------------------------------------------------------------
// Scratch (device globals: allocation-free per harness rules)
// ---------------------------------------------------------------------------
__device__ float g_q[(size_t)ROWS * NH * HD];
__device__ float g_k[(size_t)ROWS * NKV * HD];
__device__ float g_v[(size_t)ROWS * NKV * HD];
__device__ float g_o[(size_t)ROWS * NH * HD];

// shared big split buffers (used by wq-GEMM then reused by wo-GEMM)
__device__ uint32_t g_wbh[(size_t)HID * NH * HD];   // 64 MB
__device__ uint32_t g_wbl[(size_t)HID * NH * HD];   // 64 MB
// small split buffers for wk / wv
__device__ uint32_t g_wkh[(size_t)HID * NKV * HD];
__device__ uint32_t g_wkl[(size_t)HID * NKV * HD];
__device__ uint32_t g_wvh[(size_t)HID * NKV * HD];
__device__ uint32_t g_wvl[(size_t)HID * NKV * HD];

// ---------------------------------------------------------------------------
// tf32 helpers
// ---------------------------------------------------------------------------
__device__ __forceinline__ uint32_t f2tf32(float x) {
    uint32_t r;
    asm("cvt.rna.tf32.f32 %0, %1;" : "=r"(r) : "f"(x));
    return r;
}

__device__ __forceinline__ void mma_tf32(float (&d)[4], const uint32_t (&a)[4],
                                         const uint32_t (&b)[2]) {
    asm volatile(
        "mma.sync.aligned.m16n8k8.row.col.f32.tf32.tf32.f32 "
        "{%0,%1,%2,%3}, {%4,%5,%6,%7}, {%8,%9}, {%0,%1,%2,%3};\n"
        : "+f"(d[0]), "+f"(d[1]), "+f"(d[2]), "+f"(d[3])
        : "r"(a[0]), "r"(a[1]), "r"(a[2]), "r"(a[3]), "r"(b[0]), "r"(b[1]));
}

__device__ __forceinline__ void cp_async16(uint32_t saddr, const void* gptr) {
    asm volatile("cp.async.cg.shared.global [%0], [%1], 16;\n"
                 :: "r"(saddr), "l"(gptr));
}
__device__ __forceinline__ void cp_commit() {
    asm volatile("cp.async.commit_group;\n");
}
__device__ __forceinline__ void cp_wait_all() {
    asm volatile("cp.async.wait_group 0;\n");
}

// ---------------------------------------------------------------------------
// Weight split kernel: fp32 -> (hi, lo) tf32
// ---------------------------------------------------------------------------
__global__ void split_kernel(const float* __restrict__ src,
                             uint32_t* __restrict__ hi,
                             uint32_t* __restrict__ lo, int n4)
{
    int i = blockIdx.x * blockDim.x + threadIdx.x;
    if (i >= n4) return;
    float4 v = reinterpret_cast<const float4*>(src)[i];
    uint4 h, l;
    h.x = f2tf32(v.x); l.x = f2tf32(v.x - __uint_as_float(h.x));
    h.y = f2tf32(v.y); l.y = f2tf32(v.y - __uint_as_float(h.y));
    h.z = f2tf32(v.z); l.z = f2tf32(v.z - __uint_as_float(h.z));
    h.w = f2tf32(v.w); l.w = f2tf32(v.w - __uint_as_float(h.w));
    reinterpret_cast<uint4*>(hi)[i] = h;
    reinterpret_cast<uint4*>(lo)[i] = l;
}

// ---------------------------------------------------------------------------
// 3xTF32 GEMM v2: A fp32 (split in kernel), B pre-split hi/lo (cp.async).
// C[M,N] = A[M,K] @ B[K,N] row-major. Block 128x128, BK=16, 256 threads,
// 8 warps 4(M)x2(N), warp tile 32x64. Double-buffered. 2 CTAs/SM.
// ---------------------------------------------------------------------------
constexpr int G2_AH  = 128 * 20;    // 2560 u32
constexpr int G2_BH  = 16 * 136;    // 2176 u32
constexpr int G2_BUF = 2 * G2_AH + 2 * G2_BH;   // 9472 u32
constexpr int G2_SMEM_BYTES = 2 * G2_BUF * 4;   // 75776 B

__global__ void __launch_bounds__(256, 2)
tf32_gemm2_kernel(const float* __restrict__ A,
                  const uint32_t* __restrict__ Bhg,
                  const uint32_t* __restrict__ Blg,
                  float* __restrict__ C, int M, int N, int K)
{
    extern __shared__ uint32_t gsm[];

    const int tid  = threadIdx.x;
    const int lane = tid & 31;
    const int warp = tid >> 5;
    const int g    = lane >> 2;
    const int tg   = lane & 3;
    const int wm   = (warp & 3) * 32;
    const int wn   = (warp >> 2) * 64;

    A   += (size_t)blockIdx.y * 128 * K;
    Bhg += (size_t)blockIdx.x * 128;
    Blg += (size_t)blockIdx.x * 128;
    C   += (size_t)blockIdx.y * 128 * N + (size_t)blockIdx.x * 128;

    const uint32_t smem_base = (uint32_t)__cvta_generic_to_shared(gsm);

    const int arow = tid >> 2;          // 0..63 (slot1 adds 64)
    const int ac   = (tid & 3) * 4;
    const int br   = tid >> 5;          // 0..7  (slot1 adds 8)
    const int bc   = (tid & 31) * 4;

    float4 rA[2];

    auto ldA = [&](int k0) {
        rA[0] = *reinterpret_cast<const float4*>(A + (size_t)arow * K + k0 + ac);
        rA[1] = *reinterpret_cast<const float4*>(A + (size_t)(arow + 64) * K + k0 + ac);
    };
    auto cpB = [&](int k0, int buf) {
        uint32_t bhb = smem_base + (buf * G2_BUF + 2 * G2_AH) * 4;
        uint32_t blb = bhb + G2_BH * 4;
        cp_async16(bhb + (br * 136 + bc) * 4,       Bhg + (size_t)(k0 + br) * N + bc);
        cp_async16(bhb + ((br + 8) * 136 + bc) * 4, Bhg + (size_t)(k0 + br + 8) * N + bc);
        cp_async16(blb + (br * 136 + bc) * 4,       Blg + (size_t)(k0 + br) * N + bc);
        cp_async16(blb + ((br + 8) * 136 + bc) * 4, Blg + (size_t)(k0 + br + 8) * N + bc);
    };
    auto stA = [&](int buf) {
        uint32_t* Ah = gsm + buf * G2_BUF;
        uint32_t* Al = Ah + G2_AH;
        #pragma unroll
        for (int s = 0; s < 2; s++) {
            int row = arow + s * 64;
            float f[4] = {rA[s].x, rA[s].y, rA[s].z, rA[s].w};
            uint4 hv, lv;
            hv.x = f2tf32(f[0]); lv.x = f2tf32(f[0] - __uint_as_float(hv.x));
            hv.y = f2tf32(f[1]); lv.y = f2tf32(f[1] - __uint_as_float(hv.y));
            hv.z = f2tf32(f[2]); lv.z = f2tf32(f[2] - __uint_as_float(hv.z));
            hv.w = f2tf32(f[3]); lv.w = f2tf32(f[3] - __uint_as_float(hv.w));
            *reinterpret_cast<uint4*>(&Ah[row * 20 + ac]) = hv;
            *reinterpret_cast<uint4*>(&Al[row * 20 + ac]) = lv;
        }
    };

    // preamble: fill buffer 0
    ldA(0);
    cpB(0, 0);
    cp_commit();
    stA(0);
    cp_wait_all();
    __syncthreads();

    float acc[2][8][4] = {};
    const int nkt = K / 16;

    for (int kt = 0; kt < nkt; kt++) {
        const int cur = kt & 1;
        const bool more = (kt + 1 < nkt);
        if (more) {
            ldA((kt + 1) * 16);
            cpB((kt + 1) * 16, cur ^ 1);
            cp_commit();
        }

        uint32_t* Ah = gsm + cur * G2_BUF;
        uint32_t* Al = Ah + G2_AH;
        uint32_t* Bh = Al + G2_AH;
        uint32_t* Bl = Bh + G2_BH;

        #pragma unroll
        for (int ko = 0; ko < 2; ko++) {
            uint32_t ah[2][4], al_[2][4];
            #pragma unroll
            for (int i = 0; i < 2; i++) {
                int r0 = wm + 16 * i + g;
                int c0 = 8 * ko + tg;
                ah[i][0]  = Ah[r0 * 20 + c0];       ah[i][1]  = Ah[(r0 + 8) * 20 + c0];
                ah[i][2]  = Ah[r0 * 20 + c0 + 4];   ah[i][3]  = Ah[(r0 + 8) * 20 + c0 + 4];
                al_[i][0] = Al[r0 * 20 + c0];       al_[i][1] = Al[(r0 + 8) * 20 + c0];
                al_[i][2] = Al[r0 * 20 + c0 + 4];   al_[i][3] = Al[(r0 + 8) * 20 + c0 + 4];
            }
            #pragma unroll
            for (int j = 0; j < 8; j++) {
                int col = wn + 8 * j + g;
                int r0  = 8 * ko + tg;
                uint32_t bh[2] = {Bh[r0 * 136 + col], Bh[(r0 + 4) * 136 + col]};
                uint32_t bl[2] = {Bl[r0 * 136 + col], Bl[(r0 + 4) * 136 + col]};
                #pragma unroll
                for (int i = 0; i < 2; i++) {
                    mma_tf32(acc[i][j], ah[i],  bh);
                    mma_tf32(acc[i][j], al_[i], bh);
                    mma_tf32(acc[i][j], ah[i],  bl);
                }
            }
        }
        if (more) stA(cur ^ 1);
        cp_wait_all();
        __syncthreads();
    }

    #pragma unroll
    for (int i = 0; i < 2; i++) {
        #pragma unroll
        for (int j = 0; j < 8; j++) {
            int row = wm + 16 * i + g;
            int col = wn + 8 * j + 2 * tg;
            float2 v01; v01.x = acc[i][j][0]; v01.y = acc[i][j][1];
            float2 v23; v23.x = acc[i][j][2]; v23.y = acc[i][j][3];
            *reinterpret_cast<float2*>(C + (size_t)row * N + col)       = v01;
            *reinterpret_cast<float2*>(C + (size_t)(row + 8) * N + col) = v23;
        }
    }
}

// ---------------------------------------------------------------------------
// RoPE (rotate-half), in place.
// ---------------------------------------------------------------------------
__global__ void rope_kernel(float* __restrict__ t,
                            const float* __restrict__ cosb,
                            const float* __restrict__ sinb,
                            int nheads, int total)
{
    int idx = blockIdx.x * blockDim.x + threadIdx.x;
    if (idx >= total) return;
    int d   = idx & 63;
    int tmp = idx >> 6;
    int hh  = tmp % nheads;
    int row = tmp / nheads;
    int s   = row & (SS - 1);
    size_t base = (size_t)row * nheads * HD + (size_t)hh * HD;
    float c  = cosb[s * 64 + d];
    float si = sinb[s * 64 + d];
    float x1 = t[base + d];
    float x2 = t[base + 64 + d];
    t[base + d]      = x1 * c  - x2 * si;
    t[base + 64 + d] = x1 * si + x2 * c;
}

// ---------------------------------------------------------------------------
// Flash attention, tensor cores (3xTF32), causal. (passing round-4 version)
// ---------------------------------------------------------------------------
constexpr int QSTR = 132, KSTR = 132, VSTR = 136, PSTR = 68, SSTR = 65;
constexpr int F_SM_FLOATS = 64*QSTR*2 + 64*KSTR*2 + 64*VSTR + 64*SSTR + 64*PSTR*2 + 192;
constexpr int F_SM_BYTES  = F_SM_FLOATS * 4;   // 222208 B

__global__ void __launch_bounds__(256)
flash_mma_kernel(const float* __restrict__ Qg, const float* __restrict__ Kg,
                 const float* __restrict__ Vg, float* __restrict__ Og)
{
    extern __shared__ float fsm[];
    float* Qh = fsm;               float* Ql = Qh + 64 * QSTR;
    float* Kh = Ql + 64 * QSTR;    float* Kl = Kh + 64 * KSTR;
    float* Vs = Kl + 64 * KSTR;
    float* Sr = Vs + 64 * VSTR;
    float* Ph = Sr + 64 * SSTR;    float* Pl = Ph + 64 * PSTR;
    float* s_m = Pl + 64 * PSTR;   float* s_l = s_m + 64;   float* s_c = s_l + 64;

    const int tid  = threadIdx.x;
    const int lane = tid & 31;
    const int warp = tid >> 5;
    const int g    = lane >> 2;
    const int tg   = lane & 3;
    const int wm   = (warp & 3) * 16;
    const int wnS  = (warp >> 2) * 32;
    const int wnP  = (warp >> 2) * 64;

    const int qtile = gridDim.x - 1 - blockIdx.x;
    const int bh  = blockIdx.y;
    const int b   = bh / NH;
    const int h   = bh % NH;
    const int kvh = h / (NH / NKV);
    const int row0 = b * SS + qtile * 64;
    const float scale = rsqrtf((float)HD);

    {
        const float* qg = Qg + (size_t)row0 * (NH * HD) + (size_t)h * HD;
        #pragma unroll
        for (int i = 0; i < 8; i++) {
            int idx = tid + i * 256;
            int r   = idx >> 5;
            int dd  = (idx & 31) * 4;
            float4 v = *reinterpret_cast<const float4*>(qg + (size_t)r * (NH * HD) + dd);
            float f[4] = {v.x * scale, v.y * scale, v.z * scale, v.w * scale};
            uint4 hv, lv;
            uint32_t t0 = f2tf32(f[0]); hv.x = t0; lv.x = f2tf32(f[0] - __uint_as_float(t0));
            uint32_t t1 = f2tf32(f[1]); hv.y = t1; lv.y = f2tf32(f[1] - __uint_as_float(t1));
            uint32_t t2 = f2tf32(f[2]); hv.z = t2; lv.z = f2tf32(f[2] - __uint_as_float(t2));
            uint32_t t3 = f2tf32(f[3]); hv.w = t3; lv.w = f2tf32(f[3] - __uint_as_float(t3));
            *reinterpret_cast<uint4*>(&Qh[r * QSTR + dd]) = hv;
            *reinterpret_cast<uint4*>(&Ql[r * QSTR + dd]) = lv;
        }
    }
    if (tid < 64) { s_m[tid] = -INFINITY; s_l[tid] = 0.f; }

    float oacc[8][4] = {};

    for (int kt = 0; kt <= qtile; kt++) {
        __syncthreads();

        {
            const float* kg = Kg + (size_t)(b * SS + kt * 64) * (NKV * HD) + (size_t)kvh * HD;
            const float* vg = Vg + (size_t)(b * SS + kt * 64) * (NKV * HD) + (size_t)kvh * HD;
            #pragma unroll
            for (int i = 0; i < 8; i++) {
                int idx = tid + i * 256;
                int r   = idx >> 5;
                int dd  = (idx & 31) * 4;
                float4 kv = *reinterpret_cast<const float4*>(kg + (size_t)r * (NKV * HD) + dd);
                float f[4] = {kv.x, kv.y, kv.z, kv.w};
                uint4 hv, lv;
                uint32_t t0 = f2tf32(f[0]); hv.x = t0; lv.x = f2tf32(f[0] - __uint_as_float(t0));
                uint32_t t1 = f2tf32(f[1]); hv.y = t1; lv.y = f2tf32(f[1] - __uint_as_float(t1));
                uint32_t t2 = f2tf32(f[2]); hv.z = t2; lv.z = f2tf32(f[2] - __uint_as_float(t2));
                uint32_t t3 = f2tf32(f[3]); hv.w = t3; lv.w = f2tf32(f[3] - __uint_as_float(t3));
                *reinterpret_cast<uint4*>(&Kh[r * KSTR + dd]) = hv;
                *reinterpret_cast<uint4*>(&Kl[r * KSTR + dd]) = lv;
                *reinterpret_cast<float4*>(&Vs[r * VSTR + dd]) =
                    *reinterpret_cast<const float4*>(vg + (size_t)r * (NKV * HD) + dd);
            }
        }
        __syncthreads();

        float sacc[4][4] = {};
        #pragma unroll
        for (int k8 = 0; k8 < 16; k8++) {
            const int k = k8 * 8;
            uint32_t ah[4], al[4];
            ah[0] = __float_as_uint(Qh[(wm + g) * QSTR + k + tg]);
            ah[1] = __float_as_uint(Qh[(wm + g + 8) * QSTR + k + tg]);
            ah[2] = __float_as_uint(Qh[(wm + g) * QSTR + k + tg + 4]);
            ah[3] = __float_as_uint(Qh[(wm + g + 8) * QSTR + k + tg + 4]);
            al[0] = __float_as_uint(Ql[(wm + g) * QSTR + k + tg]);
            al[1] = __float_as_uint(Ql[(wm + g + 8) * QSTR + k + tg]);
            al[2] = __float_as_uint(Ql[(wm + g) * QSTR + k + tg + 4]);
            al[3] = __float_as_uint(Ql[(wm + g + 8) * QSTR + k + tg + 4]);
            #pragma unroll
            for (int nt = 0; nt < 4; nt++) {
                const int col = wnS + nt * 8 + g;
                uint32_t kb[2]  = {__float_as_uint(Kh[col * KSTR + k + tg]),
                                   __float_as_uint(Kh[col * KSTR + k + tg + 4])};
                uint32_t kl2[2] = {__float_as_uint(Kl[col * KSTR + k + tg]),
                                   __float_as_uint(Kl[col * KSTR + k + tg + 4])};
                mma_tf32(sacc[nt], ah, kb);
                mma_tf32(sacc[nt], al, kb);
                mma_tf32(sacc[nt], ah, kl2);
            }
        }

        {
            const bool diag = (kt == qtile);
            const int r0 = wm + g;
            #pragma unroll
            for (int nt = 0; nt < 4; nt++) {
                int colb = wnS + nt * 8 + 2 * tg;
                float v0 = sacc[nt][0], v1 = sacc[nt][1];
                float v2 = sacc[nt][2], v3 = sacc[nt][3];
                if (diag) {
                    if (colb     > r0)     v0 = -1e30f;
                    if (colb + 1 > r0)     v1 = -1e30f;
                    if (colb     > r0 + 8) v2 = -1e30f;
                    if (colb + 1 > r0 + 8) v3 = -1e30f;
                }
                Sr[r0 * SSTR + colb]           = v0;
                Sr[r0 * SSTR + colb + 1]       = v1;
                Sr[(r0 + 8) * SSTR + colb]     = v2;
                Sr[(r0 + 8) * SSTR + colb + 1] = v3;
            }
        }
        __syncthreads();

        {
            const int orow = tid >> 2, og = tid & 3;
            const float* srow = Sr + orow * SSTR + og * 16;
            float pm = -INFINITY;
            #pragma unroll
            for (int k = 0; k < 16; k++) pm = fmaxf(pm, srow[k]);
            pm = fmaxf(pm, __shfl_xor_sync(0xffffffffu, pm, 1));
            pm = fmaxf(pm, __shfl_xor_sync(0xffffffffu, pm, 2));
            float mold = s_m[orow];
            float mnew = fmaxf(mold, pm);
            float corr = __expf(mold - mnew);
            float psum = 0.f;
            float* ph = Ph + orow * PSTR + og * 16;
            float* pl = Pl + orow * PSTR + og * 16;
            #pragma unroll
            for (int k = 0; k < 16; k++) {
                float p = __expf(srow[k] - mnew);
                uint32_t hb = f2tf32(p);
                ph[k] = __uint_as_float(hb);
                pl[k] = __uint_as_float(f2tf32(p - __uint_as_float(hb)));
                psum += p;
            }
            psum += __shfl_xor_sync(0xffffffffu, psum, 1);
            psum += __shfl_xor_sync(0xffffffffu, psum, 2);
            if (og == 0) {
                s_m[orow] = mnew;
                s_c[orow] = corr;
                s_l[orow] = s_l[orow] * corr + psum;
            }
        }
        __syncthreads();

        {
            const float c0 = s_c[wm + g], c1 = s_c[wm + g + 8];
            #pragma unroll
            for (int nt = 0; nt < 8; nt++) {
                oacc[nt][0] *= c0; oacc[nt][1] *= c0;
                oacc[nt][2] *= c1; oacc[nt][3] *= c1;
            }
            #pragma unroll
            for (int k8 = 0; k8 < 8; k8++) {
                const int k = k8 * 8;
                uint32_t pa[4], pb[4];
                pa[0] = __float_as_uint(Ph[(wm + g) * PSTR + k + tg]);
                pa[1] = __float_as_uint(Ph[(wm + g + 8) * PSTR + k + tg]);
                pa[2] = __float_as_uint(Ph[(wm + g) * PSTR + k + tg + 4]);
                pa[3] = __float_as_uint(Ph[(wm + g + 8) * PSTR + k + tg + 4]);
                pb[0] = __float_as_uint(Pl[(wm + g) * PSTR + k + tg]);
                pb[1] = __float_as_uint(Pl[(wm + g + 8) * PSTR + k + tg]);
                pb[2] = __float_as_uint(Pl[(wm + g) * PSTR + k + tg + 4]);
                pb[3] = __float_as_uint(Pl[(wm + g + 8) * PSTR + k + tg + 4]);
                #pragma unroll
                for (int nt = 0; nt < 8; nt++) {
                    const int coln = wnP + nt * 8 + g;
                    float v0 = Vs[(k + tg) * VSTR + coln];
                    float v1 = Vs[(k + tg + 4) * VSTR + coln];
                    uint32_t h0 = f2tf32(v0), h1 = f2tf32(v1);
                    uint32_t vb[2]  = {h0, h1};
                    uint32_t vl2[2] = {f2tf32(v0 - __uint_as_float(h0)),
                                       f2tf32(v1 - __uint_as_float(h1))};
                    mma_tf32(oacc[nt], pa, vb);
                    mma_tf32(oacc[nt], pb, vb);
                    mma_tf32(oacc[nt], pa, vl2);
                }
            }
        }
    }

    {
        const float inv0 = 1.f / s_l[wm + g];
        const float inv1 = 1.f / s_l[wm + g + 8];
        float* o0 = Og + (size_t)(row0 + wm + g) * (NH * HD) + (size_t)h * HD;
        float* o1 = Og + (size_t)(row0 + wm + g + 8) * (NH * HD) + (size_t)h * HD;
        #pragma unroll
        for (int nt = 0; nt < 8; nt++) {
            int col = wnP + nt * 8 + 2 * tg;
            float2 a;  a.x  = oacc[nt][0] * inv0; a.y  = oacc[nt][1] * inv0;
            float2 b2; b2.x = oacc[nt][2] * inv1; b2.y = oacc[nt][3] * inv1;
            *reinterpret_cast<float2*>(o0 + col) = a;
            *reinterpret_cast<float2*>(o1 + col) = b2;
        }
    }
}

// ---------------------------------------------------------------------------
// Launch
// ---------------------------------------------------------------------------
extern "C" void kernel_launch(void* const* d_in, const int* in_sizes, int n_in,
                              void* d_out, int out_size)
{
    const float* x  = (const float*)d_in[0];
    const float* wq = (const float*)d_in[1];
    const float* wk = (const float*)d_in[2];
    const float* wv = (const float*)d_in[3];
    const float* wo = (const float*)d_in[4];
    const float* fc = (const float*)d_in[5];
    const float* fs = (const float*)d_in[6];
    float* out = (float*)d_out;

    float *q, *k, *v, *o;
    uint32_t *wbh, *wbl, *wkh, *wkl, *wvh, *wvl;
    cudaGetSymbolAddress((void**)&q, g_q);
    cudaGetSymbolAddress((void**)&k, g_k);
    cudaGetSymbolAddress((void**)&v, g_v);
    cudaGetSymbolAddress((void**)&o, g_o);
    cudaGetSymbolAddress((void**)&wbh, g_wbh);
    cudaGetSymbolAddress((void**)&wbl, g_wbl);
    cudaGetSymbolAddress((void**)&wkh, g_wkh);
    cudaGetSymbolAddress((void**)&wkl, g_wkl);
    cudaGetSymbolAddress((void**)&wvh, g_wvh);
    cudaGetSymbolAddress((void**)&wvl, g_wvl);

    dim3 blk(256);
    const int nq = HID * NH * HD / 4;
    const int nk = HID * NKV * HD / 4;

    cudaFuncSetAttribute(tf32_gemm2_kernel, cudaFuncAttributeMaxDynamicSharedMemorySize,
                         G2_SMEM_BYTES);
    cudaFuncSetAttribute(flash_mma_kernel, cudaFuncAttributeMaxDynamicSharedMemorySize,
                         F_SM_BYTES);

    // split wq into the shared big buffer; split wk/wv into their own
    split_kernel<<<(nq + 255) / 256, 256>>>(wq, wbh, wbl, nq);
    split_kernel<<<(nk + 255) / 256, 256>>>(wk, wkh, wkl, nk);
    split_kernel<<<(nk + 255) / 256, 256>>>(wv, wvh, wvl, nk);

    // QKV projections
    tf32_gemm2_kernel<<<dim3(NH*HD/128,  ROWS/128), blk, G2_SMEM_BYTES>>>(x, wbh, wbl, q, ROWS, NH*HD,  HID);
    tf32_gemm2_kernel<<<dim3(NKV*HD/128, ROWS/128), blk, G2_SMEM_BYTES>>>(x, wkh, wkl, k, ROWS, NKV*HD, HID);
    tf32_gemm2_kernel<<<dim3(NKV*HD/128, ROWS/128), blk, G2_SMEM_BYTES>>>(x, wvh, wvl, v, ROWS, NKV*HD, HID);

    // RoPE on q and k
    {
        int tq = ROWS * NH * 64;
        int tk = ROWS * NKV * 64;
        rope_kernel<<<(tq + 255) / 256, 256>>>(q, fc, fs, NH,  tq);
        rope_kernel<<<(tk + 255) / 256, 256>>>(k, fc, fs, NKV, tk);
    }

    // Flash attention (tensor-core 3xTF32)
    flash_mma_kernel<<<dim3(SS / 64, BB * NH), blk, F_SM_BYTES>>>(q, k, v, o);

    // reuse big buffer for wo split, then output projection
    split_kernel<<<(nq + 255) / 256, 256>>>(wo, wbh, wbl, nq);
    tf32_gemm2_kernel<<<dim3(HID/128, ROWS/128), blk, G2_SMEM_BYTES>>>(o, wbh, wbl, out, ROWS, HID, HID);
}